// round 13
// baseline (speedup 1.0000x reference)
#include <cuda_runtime.h>
#include <cuda_fp16.h>
#include <cstdint>
#include <math.h>

// ---------------- problem constants ----------------
#define BS     1024
#define CHN    3
#define IMG    64
#define KP     16
#define NC     10
#define HID    1024
#define LAT    128
#define LP     16
#define PD     768
#define MROWS  (BS * LP)        // 16384

#define RECON_ELEMS (BS * CHN * IMG * IMG)
#define ML_OFFSET   RECON_ELEMS

// GEMM tile: CTA 128x128xK64, 8 warps (2M x 4N), warp 64x32
#define TMT 128
#define TNT 128
#define TKT 64
#define NTH_S 256

#define ROWH 72                              // halves per row (64 + 8 pad)
#define SA_SZ (TMT * ROWH * 2)               // 18432 B
#define SB_SZ (TNT * ROWH * 2)               // 18432 B
#define STAGE_SZ (SA_SZ + SB_SZ)             // 36864 B
#define NSTAGE 3
#define SMEM_GG (NSTAGE * STAGE_SZ)          // 110592 B -> 2 CTA/SM

// ---------------- scratch ----------------
__device__ __half g_A1[(size_t)MROWS * PD];        // pure patches [16384][768]
__device__ __half g_H [(size_t)MROWS * HID];
__device__ __half g_A3[(size_t)MROWS * LAT];       // mu only [16384][128]
__device__ __half g_HD[(size_t)MROWS * HID];
__device__ __half g_W1[(size_t)HID * PD];          // enc_w1[0:768]^T
__device__ __half g_W2[(size_t)(2*LAT) * HID];     // enc_w2^T
__device__ __half g_W3[(size_t)HID * LAT];         // dec_w1[0:128]^T
__device__ __half g_W4[(size_t)PD * HID];          // dec_w2^T
__device__ float  g_CB1[(size_t)BS * HID];         // c@enc_w1[768:778] + enc_b1
__device__ float  g_CB3[(size_t)BS * HID];         // c@dec_w1[128:138] + dec_b1

// ---------------- helpers ----------------
__device__ __forceinline__ uint32_t smem_u32(const void* p) {
    uint32_t a;
    asm("{ .reg .u64 t; cvta.to.shared.u64 t, %1; cvt.u32.u64 %0, t; }"
        : "=r"(a) : "l"(p));
    return a;
}
#define CP16(dst, src) \
    asm volatile("cp.async.cg.shared.global [%0], [%1], 16;" :: "r"(dst), "l"(src) : "memory")
#define CP_COMMIT() asm volatile("cp.async.commit_group;" ::: "memory")
#define CP_WAIT(n)  asm volatile("cp.async.wait_group %0;" :: "n"(n) : "memory")

__device__ __forceinline__ void ldsm_x4(uint32_t& r0, uint32_t& r1, uint32_t& r2,
                                        uint32_t& r3, uint32_t addr) {
    asm volatile("ldmatrix.sync.aligned.m8n8.x4.shared.b16 {%0,%1,%2,%3}, [%4];"
                 : "=r"(r0), "=r"(r1), "=r"(r2), "=r"(r3) : "r"(addr));
}
__device__ __forceinline__ void mma_f16(float c[4],
                                        uint32_t a0, uint32_t a1, uint32_t a2, uint32_t a3,
                                        uint32_t b0, uint32_t b1) {
    asm volatile(
        "mma.sync.aligned.m16n8k16.row.col.f32.f16.f16.f32 "
        "{%0,%1,%2,%3}, {%4,%5,%6,%7}, {%8,%9}, {%0,%1,%2,%3};"
        : "+f"(c[0]), "+f"(c[1]), "+f"(c[2]), "+f"(c[3])
        : "r"(a0), "r"(a1), "r"(a2), "r"(a3), "r"(b0), "r"(b1));
}

// ---------------- fused prep (one launch) ----------------
#define PREP_PATCH_BLKS 8192
#define PREP_TRANS_BLKS 1920
#define PREP_CB_BLKS    8192
#define PREP_BLKS (PREP_PATCH_BLKS + PREP_TRANS_BLKS + PREP_CB_BLKS)

__global__ __launch_bounds__(256)
void prep_all(const float* __restrict__ x, const float* __restrict__ c,
              const float* __restrict__ enc_w1, const float* __restrict__ enc_b1,
              const float* __restrict__ enc_w2,
              const float* __restrict__ dec_w1, const float* __restrict__ dec_b1,
              const float* __restrict__ dec_w2) {
    __shared__ float tile[32][33];
    int blk = blockIdx.x;
    int tid = threadIdx.x;

    if (blk < PREP_PATCH_BLKS) {
        int row = blk * 2 + (tid >> 7);
        int t = tid & 127;
        int b = row >> 4, l = row & 15;
        int oh = l >> 2, ow = l & 3;
        const float* xb = x + (size_t)b * (CHN * IMG * IMG);
        __half* arow = g_A1 + (size_t)row * PD;
        for (int j4 = t; j4 < PD / 4; j4 += 128) {
            int j = j4 * 4;
            int ch = j >> 8, kh = (j >> 4) & 15, kw = j & 15;
            float4 v = *(const float4*)(xb + ch * (IMG * IMG) + (oh * KP + kh) * IMG
                                        + ow * KP + kw);
            *(__half2*)(arow + j)     = __floats2half2_rn(v.x, v.y);
            *(__half2*)(arow + j + 2) = __floats2half2_rn(v.z, v.w);
        }
        return;
    }
    blk -= PREP_PATCH_BLKS;
    if (blk < PREP_TRANS_BLKS) {
        const float* W; __half* Wt; int K, N, Kpad, t;
        if (blk < 768)      { W = enc_w1; Wt = g_W1; K = PD;  N = HID;     Kpad = PD;  t = blk; }
        else if (blk < 1024){ W = enc_w2; Wt = g_W2; K = HID; N = 2 * LAT; Kpad = HID; t = blk - 768; }
        else if (blk < 1152){ W = dec_w1; Wt = g_W3; K = LAT; N = HID;     Kpad = LAT; t = blk - 1024; }
        else                { W = dec_w2; Wt = g_W4; K = HID; N = PD;      Kpad = HID; t = blk - 1152; }
        int ktiles = Kpad / 32;
        int kb = (t % ktiles) * 32, nb = (t / ktiles) * 32;
        int tx = tid & 31, ty = tid >> 5;
        for (int i = ty; i < 32; i += 8) {
            int k = kb + i;
            tile[i][tx] = (k < K) ? W[(size_t)k * N + nb + tx] : 0.0f;
        }
        __syncthreads();
        for (int i = ty; i < 32; i += 8)
            Wt[(size_t)(nb + i) * Kpad + kb + tx] = __float2half_rn(tile[tx][i]);
        return;
    }
    blk -= PREP_TRANS_BLKS;
    {
        int z = blk >> 12;
        int rem = blk & 4095;
        int b = rem >> 2;
        int n = (rem & 3) * 256 + tid;
        const float* W  = z ? dec_w1 : enc_w1;
        const float* bb = z ? dec_b1 : enc_b1;
        int krow = z ? LAT : PD;
        float* out = (z ? g_CB3 : g_CB1) + (size_t)b * HID + n;
        float acc = bb[n];
        const float* cb = c + b * NC;
#pragma unroll
        for (int j = 0; j < NC; j++)
            acc = fmaf(cb[j], W[(size_t)(krow + j) * HID + n], acc);
        *out = acc;
    }
}

// ---------------- fp16 mma.sync GEMM (warp 64x32, 3-stage, 2 CTA/SM) -------
// EPI 0: ReLU -> fp16 C (ldc)
// EPI 1: mu_logvar -> fp32 C ([b][f][l], staged) + mu -> fp16 C2 (stride LAT)
// EPI 2: sigmoid + depatchify -> fp32 C (recon), staged coalesced
// BIASMAT 0: bias[n]; 1: bias[b][n] (ld = HID)
template <int EPI, int BIASMAT>
__global__ __launch_bounds__(NTH_S, 2)
void gemm_mma(const __half* __restrict__ A, int kpad,
              const __half* __restrict__ Bt,
              const float* __restrict__ bias,
              void* __restrict__ Cv, __half* __restrict__ C2,
              int ldc, int nchunks) {
    extern __shared__ char smem[];
    const uint32_t sb = smem_u32(smem);

    const int tid  = threadIdx.x;
    const int wid  = tid >> 5;
    const int lane = tid & 31;
    const int wm   = wid & 1;
    const int wn   = wid >> 1;
    const int m0   = blockIdx.y * TMT;
    const int n0   = blockIdx.x * TNT;

    const __half* Ab = A + (size_t)m0 * kpad;
    const __half* Bb = Bt + (size_t)n0 * kpad;

    const int lg = lane >> 2;
    const int li = lane & 3;

    float bv[4][2];
    if (BIASMAT == 0) {
#pragma unroll
        for (int nt = 0; nt < 4; nt++) {
            int cc = n0 + wn * 32 + nt * 8 + li * 2;
            bv[nt][0] = __ldg(bias + cc);
            bv[nt][1] = __ldg(bias + cc + 1);
        }
    }

    float acc[4][4][4];
#pragma unroll
    for (int i = 0; i < 4; i++)
#pragma unroll
        for (int j = 0; j < 4; j++)
#pragma unroll
            for (int q = 0; q < 4; q++) acc[i][j][q] = 0.0f;

    auto load_tiles = [&](int stage, int kb) {
        uint32_t adst = sb + stage * STAGE_SZ;
        uint32_t bdst = adst + SA_SZ;
#pragma unroll
        for (int o = 0; o < 4; o++) {
            int e = o * NTH_S + tid;
            int r = e >> 3, cc = e & 7;
            CP16(adst + r * (ROWH * 2) + cc * 16,
                 Ab + (size_t)r * kpad + kb + cc * 8);
        }
#pragma unroll
        for (int o = 0; o < 4; o++) {
            int e = o * NTH_S + tid;
            int r = e >> 3, cc = e & 7;
            CP16(bdst + r * (ROWH * 2) + cc * 16,
                 Bb + (size_t)r * kpad + kb + cc * 8);
        }
    };

    load_tiles(0, 0);
    CP_COMMIT();
    load_tiles(1, TKT);
    CP_COMMIT();

    const uint32_t aOff = (uint32_t)(wm * 64 + (lane & 15)) * (ROWH * 2) + (lane >> 4) * 16;
    const uint32_t bOff = SA_SZ +
        (uint32_t)(wn * 32 + (lane & 7) + ((lane >> 4) & 1) * 8) * (ROWH * 2)
        + ((lane >> 3) & 1) * 16;

    for (int it = 0; it < nchunks; ++it) {
        if (it + 1 < nchunks) CP_WAIT(1); else CP_WAIT(0);
        __syncthreads();
        if (it + 2 < nchunks) {
            load_tiles((it + 2) % NSTAGE, (it + 2) * TKT);
            CP_COMMIT();
        }

        const uint32_t stg = sb + (it % NSTAGE) * STAGE_SZ;
        const uint32_t aB = stg + aOff;
        const uint32_t bB = stg + bOff;

#pragma unroll
        for (int ks = 0; ks < 4; ks++) {
            uint32_t a[4][4];
#pragma unroll
            for (int mt = 0; mt < 4; mt++)
                ldsm_x4(a[mt][0], a[mt][1], a[mt][2], a[mt][3],
                        aB + mt * (16 * ROWH * 2) + ks * 32);
            uint32_t b[4][2];
#pragma unroll
            for (int p = 0; p < 2; p++)
                ldsm_x4(b[2*p][0], b[2*p][1], b[2*p+1][0], b[2*p+1][1],
                        bB + p * (16 * ROWH * 2) + ks * 32);
#pragma unroll
            for (int mt = 0; mt < 4; mt++)
#pragma unroll
                for (int nt = 0; nt < 4; nt++)
                    mma_f16(acc[mt][nt], a[mt][0], a[mt][1], a[mt][2], a[mt][3],
                            b[nt][0], b[nt][1]);
        }
    }

    // ---------------- epilogue ----------------
    if (EPI == 1) {
        __syncthreads();
        float* sm = (float*)smem;   // [b_local(8)][f_local(128) stride 20][l(16)]
#pragma unroll
        for (int mt = 0; mt < 4; mt++) {
            int lr = wm * 64 + mt * 16 + lg;
            int bl = lr >> 4;
            int l  = lr & 15;
            int r  = m0 + lr;
#pragma unroll
            for (int nt = 0; nt < 4; nt++) {
                int fl = wn * 32 + nt * 8 + li * 2;
                int cc = n0 + fl;
                float v0 = acc[mt][nt][0] + bv[nt][0];
                float v1 = acc[mt][nt][1] + bv[nt][1];
                float v2 = acc[mt][nt][2] + bv[nt][0];
                float v3 = acc[mt][nt][3] + bv[nt][1];
                sm[bl * 2560 + fl * 20 + l]           = v0;
                sm[bl * 2560 + (fl + 1) * 20 + l]     = v1;
                sm[bl * 2560 + fl * 20 + l + 8]       = v2;
                sm[bl * 2560 + (fl + 1) * 20 + l + 8] = v3;
                if (cc < LAT) {
                    *(__half2*)(C2 + (size_t)r * LAT + cc) = __floats2half2_rn(v0, v1);
                    *(__half2*)(C2 + (size_t)(r + 8) * LAT + cc) = __floats2half2_rn(v2, v3);
                }
            }
        }
        __syncthreads();
        float* C = (float*)Cv + (size_t)(m0 >> 4) * (2 * LAT * LP) + n0 * LP;
#pragma unroll
        for (int o = 0; o < 16; o++) {
            int e = o * NTH_S + tid;
            int l4 = e & 3, f = (e >> 2) & 127, b = e >> 9;
            float4 v = *(float4*)(sm + b * 2560 + f * 20 + l4 * 4);
            *(float4*)(C + (size_t)b * (2 * LAT * LP) + f * LP + l4 * 4) = v;
        }
        return;
    }

    if (EPI == 2) {
        // sigmoid + staged coalesced depatchify
        __syncthreads();
        float* sm = (float*)smem;   // [128][132]
#pragma unroll
        for (int mt = 0; mt < 4; mt++) {
            int rl = wm * 64 + mt * 16 + lg;
#pragma unroll
            for (int nt = 0; nt < 4; nt++) {
                int cl = wn * 32 + nt * 8 + li * 2;
                float v0 = 1.0f / (1.0f + __expf(-(acc[mt][nt][0] + bv[nt][0])));
                float v1 = 1.0f / (1.0f + __expf(-(acc[mt][nt][1] + bv[nt][1])));
                float v2 = 1.0f / (1.0f + __expf(-(acc[mt][nt][2] + bv[nt][0])));
                float v3 = 1.0f / (1.0f + __expf(-(acc[mt][nt][3] + bv[nt][1])));
                sm[rl * 132 + cl]           = v0;
                sm[rl * 132 + cl + 1]       = v1;
                sm[(rl + 8) * 132 + cl]     = v2;
                sm[(rl + 8) * 132 + cl + 1] = v3;
            }
        }
        __syncthreads();
        const int ch  = n0 >> 8;
        const int khb = (n0 >> 4) & 15;       // 0 or 8
        const int b0  = m0 >> 4;
        float* Cb = (float*)Cv + (size_t)ch * (IMG * IMG);
#pragma unroll
        for (int o = 0; o < 16; o++) {
            int e = o * NTH_S + tid;          // 0..4095 float4s
            int imgrow = e >> 4;              // 0..255 : (bl, oh, khl)
            int seg = e & 15;                 // 16 float4 per 64-px img row
            int bl  = imgrow >> 5;
            int oh  = (imgrow >> 3) & 3;
            int khl = imgrow & 7;
            int ow  = seg >> 2;
            int l4  = seg & 3;
            int m   = bl * 16 + oh * 4 + ow;
            float4 v = *(float4*)(sm + m * 132 + khl * 16 + l4 * 4);
            float* op = Cb + (size_t)(b0 + bl) * (CHN * IMG * IMG)
                      + (oh * KP + khb + khl) * IMG + ow * KP + l4 * 4;
            *(float4*)op = v;
        }
        return;
    }

    // EPI 0: ReLU -> fp16 C
#pragma unroll
    for (int mt = 0; mt < 4; mt++) {
        int r = m0 + wm * 64 + mt * 16 + lg;
        const float* bp = BIASMAT ? (bias + (size_t)((m0 + wm * 64 + mt * 16) >> 4) * HID)
                                  : nullptr;
#pragma unroll
        for (int nt = 0; nt < 4; nt++) {
            int cc = n0 + wn * 32 + nt * 8 + li * 2;
            float b0, b1;
            if (BIASMAT) { b0 = __ldg(bp + cc); b1 = __ldg(bp + cc + 1); }
            else         { b0 = bv[nt][0];      b1 = bv[nt][1]; }
            float v0 = acc[mt][nt][0] + b0;
            float v1 = acc[mt][nt][1] + b1;
            float v2 = acc[mt][nt][2] + b0;
            float v3 = acc[mt][nt][3] + b1;
            __half* C = (__half*)Cv;
            *(__half2*)(C + (size_t)r * ldc + cc) =
                __floats2half2_rn(fmaxf(v0, 0.f), fmaxf(v1, 0.f));
            *(__half2*)(C + (size_t)(r + 8) * ldc + cc) =
                __floats2half2_rn(fmaxf(v2, 0.f), fmaxf(v3, 0.f));
        }
    }
}

// ---------------- launch ----------------
extern "C" void kernel_launch(void* const* d_in, const int* in_sizes, int n_in,
                              void* d_out, int out_size) {
    const float* x      = (const float*)d_in[0];
    const float* c      = (const float*)d_in[1];
    const float* enc_w1 = (const float*)d_in[2];
    const float* enc_b1 = (const float*)d_in[3];
    const float* enc_w2 = (const float*)d_in[4];
    const float* enc_b2 = (const float*)d_in[5];
    const float* dec_w1 = (const float*)d_in[6];
    const float* dec_b1 = (const float*)d_in[7];
    const float* dec_w2 = (const float*)d_in[8];
    const float* dec_b2 = (const float*)d_in[9];
    float* out = (float*)d_out;

    __half *A1, *H, *A3, *HD, *W1, *W2, *W3, *W4;
    float *CB1, *CB3;
    cudaGetSymbolAddress((void**)&A1,  g_A1);
    cudaGetSymbolAddress((void**)&H,   g_H);
    cudaGetSymbolAddress((void**)&A3,  g_A3);
    cudaGetSymbolAddress((void**)&HD,  g_HD);
    cudaGetSymbolAddress((void**)&W1,  g_W1);
    cudaGetSymbolAddress((void**)&W2,  g_W2);
    cudaGetSymbolAddress((void**)&W3,  g_W3);
    cudaGetSymbolAddress((void**)&W4,  g_W4);
    cudaGetSymbolAddress((void**)&CB1, g_CB1);
    cudaGetSymbolAddress((void**)&CB3, g_CB3);

    cudaFuncSetAttribute(gemm_mma<0,1>, cudaFuncAttributeMaxDynamicSharedMemorySize, SMEM_GG);
    cudaFuncSetAttribute(gemm_mma<1,0>, cudaFuncAttributeMaxDynamicSharedMemorySize, SMEM_GG);
    cudaFuncSetAttribute(gemm_mma<2,0>, cudaFuncAttributeMaxDynamicSharedMemorySize, SMEM_GG);

    // fused prep (single launch)
    prep_all<<<PREP_BLKS, 256>>>(x, c, enc_w1, enc_b1, enc_w2, dec_w1, dec_b1, dec_w2);

    // GEMM1: A1[16384 x 768] * W1^T -> H (ReLU, fp16), bias = CB1[b][n]
    gemm_mma<0,1><<<dim3(HID / TNT, MROWS / TMT), NTH_S, SMEM_GG>>>(
        A1, PD, W1, CB1, H, nullptr, HID, PD / TKT);
    // GEMM2: H * W2^T -> mu_logvar (fp32, staged) + mu -> A3 (fp16), N=256
    gemm_mma<1,0><<<dim3((2 * LAT) / TNT, MROWS / TMT), NTH_S, SMEM_GG>>>(
        H, HID, W2, enc_b2, out + ML_OFFSET, A3, 0, HID / TKT);
    // GEMM3: A3[16384 x 128] * W3^T -> HD (ReLU, fp16), bias = CB3[b][n]
    gemm_mma<0,1><<<dim3(HID / TNT, MROWS / TMT), NTH_S, SMEM_GG>>>(
        A3, LAT, W3, CB3, HD, nullptr, HID, LAT / TKT);
    // GEMM4: HD * W4^T -> sigmoid + staged depatchify (fp32), N=768
    gemm_mma<2,0><<<dim3(PD / TNT, MROWS / TMT), NTH_S, SMEM_GG>>>(
        HD, HID, W4, dec_b2, out, nullptr, 0, HID / TKT);
}

// round 14
// speedup vs baseline: 1.0263x; 1.0263x over previous
#include <cuda_runtime.h>
#include <cuda_fp16.h>
#include <cstdint>
#include <math.h>

// ---------------- problem constants ----------------
#define BS     1024
#define CHN    3
#define IMG    64
#define KP     16
#define NC     10
#define HID    1024
#define LAT    128
#define LP     16
#define PD     768
#define MROWS  (BS * LP)        // 16384

#define RECON_ELEMS (BS * CHN * IMG * IMG)
#define ML_OFFSET   RECON_ELEMS

// GEMM tile: CTA 128x128xK64, 8 warps (2M x 4N), warp 64x32
#define TMT 128
#define TNT 128
#define TKT 64
#define NTH_S 256

#define ROWH 72                              // halves per row (64 + 8 pad)
#define SA_SZ (TMT * ROWH * 2)               // 18432 B
#define SB_SZ (TNT * ROWH * 2)               // 18432 B
#define STAGE_SZ (SA_SZ + SB_SZ)             // 36864 B
#define NSTAGE 3
#define SMEM_GG (NSTAGE * STAGE_SZ)          // 110592 B -> 2 CTA/SM
#define SMEM_P  (2 * SA_SZ + 2 * (2 * SB_SZ))// 110592 B (gemm3p)

// ---------------- scratch ----------------
__device__ __half g_A1[(size_t)MROWS * PD];        // pure patches [16384][768]
__device__ __half g_H [(size_t)MROWS * HID];
__device__ __half g_A3[(size_t)MROWS * LAT];       // mu only [16384][128]
__device__ __half g_HD[(size_t)MROWS * HID];
__device__ __half g_W1[(size_t)HID * PD];          // enc_w1[0:768]^T
__device__ __half g_W2[(size_t)(2*LAT) * HID];     // enc_w2^T
__device__ __half g_W3[(size_t)HID * LAT];         // dec_w1[0:128]^T
__device__ __half g_W4[(size_t)PD * HID];          // dec_w2^T
__device__ float  g_CB1[(size_t)BS * HID];         // c@enc_w1[768:778] + enc_b1
__device__ float  g_CB3[(size_t)BS * HID];         // c@dec_w1[128:138] + dec_b1

// ---------------- helpers ----------------
__device__ __forceinline__ uint32_t smem_u32(const void* p) {
    uint32_t a;
    asm("{ .reg .u64 t; cvta.to.shared.u64 t, %1; cvt.u32.u64 %0, t; }"
        : "=r"(a) : "l"(p));
    return a;
}
#define CP16(dst, src) \
    asm volatile("cp.async.cg.shared.global [%0], [%1], 16;" :: "r"(dst), "l"(src) : "memory")
#define CP_COMMIT() asm volatile("cp.async.commit_group;" ::: "memory")
#define CP_WAIT(n)  asm volatile("cp.async.wait_group %0;" :: "n"(n) : "memory")

__device__ __forceinline__ void ldsm_x4(uint32_t& r0, uint32_t& r1, uint32_t& r2,
                                        uint32_t& r3, uint32_t addr) {
    asm volatile("ldmatrix.sync.aligned.m8n8.x4.shared.b16 {%0,%1,%2,%3}, [%4];"
                 : "=r"(r0), "=r"(r1), "=r"(r2), "=r"(r3) : "r"(addr));
}
__device__ __forceinline__ void mma_f16(float c[4],
                                        uint32_t a0, uint32_t a1, uint32_t a2, uint32_t a3,
                                        uint32_t b0, uint32_t b1) {
    asm volatile(
        "mma.sync.aligned.m16n8k16.row.col.f32.f16.f16.f32 "
        "{%0,%1,%2,%3}, {%4,%5,%6,%7}, {%8,%9}, {%0,%1,%2,%3};"
        : "+f"(c[0]), "+f"(c[1]), "+f"(c[2]), "+f"(c[3])
        : "r"(a0), "r"(a1), "r"(a2), "r"(a3), "r"(b0), "r"(b1));
}

// ---------------- fused prep (one launch) ----------------
#define PREP_PATCH_BLKS 8192
#define PREP_TRANS_BLKS 1920
#define PREP_CB_BLKS    8192
#define PREP_BLKS (PREP_PATCH_BLKS + PREP_TRANS_BLKS + PREP_CB_BLKS)

__global__ __launch_bounds__(256)
void prep_all(const float* __restrict__ x, const float* __restrict__ c,
              const float* __restrict__ enc_w1, const float* __restrict__ enc_b1,
              const float* __restrict__ enc_w2,
              const float* __restrict__ dec_w1, const float* __restrict__ dec_b1,
              const float* __restrict__ dec_w2) {
    __shared__ float tile[32][33];
    int blk = blockIdx.x;
    int tid = threadIdx.x;

    if (blk < PREP_PATCH_BLKS) {
        int row = blk * 2 + (tid >> 7);
        int t = tid & 127;
        int b = row >> 4, l = row & 15;
        int oh = l >> 2, ow = l & 3;
        const float* xb = x + (size_t)b * (CHN * IMG * IMG);
        __half* arow = g_A1 + (size_t)row * PD;
        for (int j4 = t; j4 < PD / 4; j4 += 128) {
            int j = j4 * 4;
            int ch = j >> 8, kh = (j >> 4) & 15, kw = j & 15;
            float4 v = *(const float4*)(xb + ch * (IMG * IMG) + (oh * KP + kh) * IMG
                                        + ow * KP + kw);
            *(__half2*)(arow + j)     = __floats2half2_rn(v.x, v.y);
            *(__half2*)(arow + j + 2) = __floats2half2_rn(v.z, v.w);
        }
        return;
    }
    blk -= PREP_PATCH_BLKS;
    if (blk < PREP_TRANS_BLKS) {
        const float* W; __half* Wt; int K, N, Kpad, t;
        if (blk < 768)      { W = enc_w1; Wt = g_W1; K = PD;  N = HID;     Kpad = PD;  t = blk; }
        else if (blk < 1024){ W = enc_w2; Wt = g_W2; K = HID; N = 2 * LAT; Kpad = HID; t = blk - 768; }
        else if (blk < 1152){ W = dec_w1; Wt = g_W3; K = LAT; N = HID;     Kpad = LAT; t = blk - 1024; }
        else                { W = dec_w2; Wt = g_W4; K = HID; N = PD;      Kpad = HID; t = blk - 1152; }
        int ktiles = Kpad / 32;
        int kb = (t % ktiles) * 32, nb = (t / ktiles) * 32;
        int tx = tid & 31, ty = tid >> 5;
        for (int i = ty; i < 32; i += 8) {
            int k = kb + i;
            tile[i][tx] = (k < K) ? W[(size_t)k * N + nb + tx] : 0.0f;
        }
        __syncthreads();
        for (int i = ty; i < 32; i += 8)
            Wt[(size_t)(nb + i) * Kpad + kb + tx] = __float2half_rn(tile[tx][i]);
        return;
    }
    blk -= PREP_TRANS_BLKS;
    {
        int z = blk >> 12;
        int rem = blk & 4095;
        int b = rem >> 2;
        int n = (rem & 3) * 256 + tid;
        const float* W  = z ? dec_w1 : enc_w1;
        const float* bb = z ? dec_b1 : enc_b1;
        int krow = z ? LAT : PD;
        float* out = (z ? g_CB3 : g_CB1) + (size_t)b * HID + n;
        float acc = bb[n];
        const float* cb = c + b * NC;
#pragma unroll
        for (int j = 0; j < NC; j++)
            acc = fmaf(cb[j], W[(size_t)(krow + j) * HID + n], acc);
        *out = acc;
    }
}

// ---------------- round-9 GEMM: 256 thr, warp 64x32, 3-stage ---------------
// EPI 0: ReLU -> fp16 C (ldc)
// EPI 1: mu_logvar -> fp32 C ([b][f][l], staged) + mu -> fp16 C2 (stride LAT)
// EPI 2: sigmoid + depatchify -> fp32 C (direct scatter)
// BIASMAT 0: bias[n]; 1: bias[b][n] (ld = HID)
template <int EPI, int BIASMAT>
__global__ __launch_bounds__(NTH_S, 2)
void gemm_mma(const __half* __restrict__ A, int kpad,
              const __half* __restrict__ Bt,
              const float* __restrict__ bias,
              void* __restrict__ Cv, __half* __restrict__ C2,
              int ldc, int nchunks) {
    extern __shared__ char smem[];
    const uint32_t sb = smem_u32(smem);

    const int tid  = threadIdx.x;
    const int wid  = tid >> 5;
    const int lane = tid & 31;
    const int wm   = wid & 1;
    const int wn   = wid >> 1;
    const int m0   = blockIdx.y * TMT;
    const int n0   = blockIdx.x * TNT;

    const __half* Ab = A + (size_t)m0 * kpad;
    const __half* Bb = Bt + (size_t)n0 * kpad;

    const int lg = lane >> 2;
    const int li = lane & 3;

    float bv[4][2];
    if (BIASMAT == 0) {
#pragma unroll
        for (int nt = 0; nt < 4; nt++) {
            int cc = n0 + wn * 32 + nt * 8 + li * 2;
            bv[nt][0] = __ldg(bias + cc);
            bv[nt][1] = __ldg(bias + cc + 1);
        }
    }

    float acc[4][4][4];
#pragma unroll
    for (int i = 0; i < 4; i++)
#pragma unroll
        for (int j = 0; j < 4; j++)
#pragma unroll
            for (int q = 0; q < 4; q++) acc[i][j][q] = 0.0f;

    auto load_tiles = [&](int stage, int kb) {
        uint32_t adst = sb + stage * STAGE_SZ;
        uint32_t bdst = adst + SA_SZ;
#pragma unroll
        for (int o = 0; o < 4; o++) {
            int e = o * NTH_S + tid;
            int r = e >> 3, cc = e & 7;
            CP16(adst + r * (ROWH * 2) + cc * 16,
                 Ab + (size_t)r * kpad + kb + cc * 8);
        }
#pragma unroll
        for (int o = 0; o < 4; o++) {
            int e = o * NTH_S + tid;
            int r = e >> 3, cc = e & 7;
            CP16(bdst + r * (ROWH * 2) + cc * 16,
                 Bb + (size_t)r * kpad + kb + cc * 8);
        }
    };

    load_tiles(0, 0);
    CP_COMMIT();
    load_tiles(1, TKT);
    CP_COMMIT();

    const uint32_t aOff = (uint32_t)(wm * 64 + (lane & 15)) * (ROWH * 2) + (lane >> 4) * 16;
    const uint32_t bOff = SA_SZ +
        (uint32_t)(wn * 32 + (lane & 7) + ((lane >> 4) & 1) * 8) * (ROWH * 2)
        + ((lane >> 3) & 1) * 16;

    for (int it = 0; it < nchunks; ++it) {
        if (it + 1 < nchunks) CP_WAIT(1); else CP_WAIT(0);
        __syncthreads();
        if (it + 2 < nchunks) {
            load_tiles((it + 2) % NSTAGE, (it + 2) * TKT);
            CP_COMMIT();
        }

        const uint32_t stg = sb + (it % NSTAGE) * STAGE_SZ;
        const uint32_t aB = stg + aOff;
        const uint32_t bB = stg + bOff;

#pragma unroll
        for (int ks = 0; ks < 4; ks++) {
            uint32_t a[4][4];
#pragma unroll
            for (int mt = 0; mt < 4; mt++)
                ldsm_x4(a[mt][0], a[mt][1], a[mt][2], a[mt][3],
                        aB + mt * (16 * ROWH * 2) + ks * 32);
            uint32_t b[4][2];
#pragma unroll
            for (int p = 0; p < 2; p++)
                ldsm_x4(b[2*p][0], b[2*p][1], b[2*p+1][0], b[2*p+1][1],
                        bB + p * (16 * ROWH * 2) + ks * 32);
#pragma unroll
            for (int mt = 0; mt < 4; mt++)
#pragma unroll
                for (int nt = 0; nt < 4; nt++)
                    mma_f16(acc[mt][nt], a[mt][0], a[mt][1], a[mt][2], a[mt][3],
                            b[nt][0], b[nt][1]);
        }
    }

    // ---------------- epilogue ----------------
    if (EPI == 1) {
        __syncthreads();
        float* sm = (float*)smem;   // [b_local(8)][f_local(128) stride 20][l(16)]
#pragma unroll
        for (int mt = 0; mt < 4; mt++) {
            int lr = wm * 64 + mt * 16 + lg;
            int bl = lr >> 4;
            int l  = lr & 15;
            int r  = m0 + lr;
#pragma unroll
            for (int nt = 0; nt < 4; nt++) {
                int fl = wn * 32 + nt * 8 + li * 2;
                int cc = n0 + fl;
                float v0 = acc[mt][nt][0] + bv[nt][0];
                float v1 = acc[mt][nt][1] + bv[nt][1];
                float v2 = acc[mt][nt][2] + bv[nt][0];
                float v3 = acc[mt][nt][3] + bv[nt][1];
                sm[bl * 2560 + fl * 20 + l]           = v0;
                sm[bl * 2560 + (fl + 1) * 20 + l]     = v1;
                sm[bl * 2560 + fl * 20 + l + 8]       = v2;
                sm[bl * 2560 + (fl + 1) * 20 + l + 8] = v3;
                if (cc < LAT) {
                    *(__half2*)(C2 + (size_t)r * LAT + cc) = __floats2half2_rn(v0, v1);
                    *(__half2*)(C2 + (size_t)(r + 8) * LAT + cc) = __floats2half2_rn(v2, v3);
                }
            }
        }
        __syncthreads();
        float* C = (float*)Cv + (size_t)(m0 >> 4) * (2 * LAT * LP) + n0 * LP;
#pragma unroll
        for (int o = 0; o < 16; o++) {
            int e = o * NTH_S + tid;
            int l4 = e & 3, f = (e >> 2) & 127, b = e >> 9;
            float4 v = *(float4*)(sm + b * 2560 + f * 20 + l4 * 4);
            *(float4*)(C + (size_t)b * (2 * LAT * LP) + f * LP + l4 * 4) = v;
        }
        return;
    }

#pragma unroll
    for (int mt = 0; mt < 4; mt++) {
        int r = m0 + wm * 64 + mt * 16 + lg;
        const float* bp = BIASMAT ? (bias + (size_t)((m0 + wm * 64 + mt * 16) >> 4) * HID)
                                  : nullptr;
#pragma unroll
        for (int nt = 0; nt < 4; nt++) {
            int cc = n0 + wn * 32 + nt * 8 + li * 2;
            float b0, b1;
            if (BIASMAT) { b0 = __ldg(bp + cc); b1 = __ldg(bp + cc + 1); }
            else         { b0 = bv[nt][0];      b1 = bv[nt][1]; }
            float v0 = acc[mt][nt][0] + b0;
            float v1 = acc[mt][nt][1] + b1;
            float v2 = acc[mt][nt][2] + b0;
            float v3 = acc[mt][nt][3] + b1;

            if (EPI == 0) {
                __half* C = (__half*)Cv;
                *(__half2*)(C + (size_t)r * ldc + cc) =
                    __floats2half2_rn(fmaxf(v0, 0.f), fmaxf(v1, 0.f));
                *(__half2*)(C + (size_t)(r + 8) * ldc + cc) =
                    __floats2half2_rn(fmaxf(v2, 0.f), fmaxf(v3, 0.f));
            } else {
                float* C = (float*)Cv;
                v0 = 1.0f / (1.0f + __expf(-v0));
                v1 = 1.0f / (1.0f + __expf(-v1));
                v2 = 1.0f / (1.0f + __expf(-v2));
                v3 = 1.0f / (1.0f + __expf(-v3));
                int ch = cc >> 8, kh = (cc >> 4) & 15, kw = cc & 15;
                {
                    int b_ = r >> 4, l = r & 15;
                    int oh = l >> 2, ow = l & 3;
                    float* op = C + (size_t)b_ * (CHN * IMG * IMG) + ch * (IMG * IMG)
                              + (oh * KP + kh) * IMG + ow * KP + kw;
                    *(float2*)op = make_float2(v0, v1);
                }
                {
                    int rr = r + 8;
                    int b_ = rr >> 4, l = rr & 15;
                    int oh = l >> 2, ow = l & 3;
                    float* op = C + (size_t)b_ * (CHN * IMG * IMG) + ch * (IMG * IMG)
                              + (oh * KP + kh) * IMG + ow * KP + kw;
                    *(float2*)op = make_float2(v2, v3);
                }
            }
        }
    }
}

// ---------------- GEMM3 persistent-A: grid=128, A3 tile loaded once --------
// HD[m0:m0+128][:] = relu(A3_tile @ W3t^T + CB3[b][n]); loops 8 n-tiles,
// B double-buffered (2 k-chunks per tile).
__global__ __launch_bounds__(NTH_S, 1)
void gemm3p(const __half* __restrict__ A3,
            const __half* __restrict__ W3t,
            const float* __restrict__ CB3,
            __half* __restrict__ HD) {
    extern __shared__ char smem[];
    const uint32_t sb  = smem_u32(smem);
    const uint32_t bBase = sb + 2 * SA_SZ;      // B buffers start

    const int tid  = threadIdx.x;
    const int wid  = tid >> 5;
    const int lane = tid & 31;
    const int wm   = wid & 1;
    const int wn   = wid >> 1;
    const int m0   = blockIdx.x * TMT;
    const int lg   = lane >> 2;
    const int li   = lane & 3;

    // load A tile (128 rows x 128 halves) once: 2 chunks
    {
        const __half* Ap = A3 + (size_t)m0 * LAT;
#pragma unroll
        for (int o = 0; o < 8; o++) {
            int e = o * NTH_S + tid;      // 0..2047
            int ck = e >> 10;
            int r  = (e >> 3) & 127;
            int cc = e & 7;
            CP16(sb + ck * SA_SZ + r * (ROWH * 2) + cc * 16,
                 Ap + (size_t)r * LAT + ck * 64 + cc * 8);
        }
    }
    CP_COMMIT();

    auto loadB = [&](int buf, int ntile) {
        const __half* Bp = W3t + (size_t)(ntile * 128) * LAT;
        uint32_t base = bBase + buf * (2 * SB_SZ);
#pragma unroll
        for (int o = 0; o < 8; o++) {
            int e = o * NTH_S + tid;
            int ck = e >> 10;
            int r  = (e >> 3) & 127;
            int cc = e & 7;
            CP16(base + ck * SB_SZ + r * (ROWH * 2) + cc * 16,
                 Bp + (size_t)r * LAT + ck * 64 + cc * 8);
        }
    };

    loadB(0, 0);
    CP_COMMIT();

    const uint32_t aOff = (uint32_t)(wm * 64 + (lane & 15)) * (ROWH * 2) + (lane >> 4) * 16;
    const uint32_t bOffL = (uint32_t)(wn * 32 + (lane & 7) + ((lane >> 4) & 1) * 8)
                           * (ROWH * 2) + ((lane >> 3) & 1) * 16;

    for (int t = 0; t < 8; t++) {
        CP_WAIT(0);
        __syncthreads();
        if (t + 1 < 8) {
            loadB((t + 1) & 1, t + 1);
            CP_COMMIT();
        }

        float acc[4][4][4];
#pragma unroll
        for (int i = 0; i < 4; i++)
#pragma unroll
            for (int j = 0; j < 4; j++)
#pragma unroll
                for (int q = 0; q < 4; q++) acc[i][j][q] = 0.0f;

#pragma unroll
        for (int ck = 0; ck < 2; ck++) {
            const uint32_t aB = sb + ck * SA_SZ + aOff;
            const uint32_t bB = bBase + (t & 1) * (2 * SB_SZ) + ck * SB_SZ + bOffL;
#pragma unroll
            for (int ks = 0; ks < 4; ks++) {
                uint32_t a[4][4];
#pragma unroll
                for (int mt = 0; mt < 4; mt++)
                    ldsm_x4(a[mt][0], a[mt][1], a[mt][2], a[mt][3],
                            aB + mt * (16 * ROWH * 2) + ks * 32);
                uint32_t b[4][2];
#pragma unroll
                for (int p = 0; p < 2; p++)
                    ldsm_x4(b[2*p][0], b[2*p][1], b[2*p+1][0], b[2*p+1][1],
                            bB + p * (16 * ROWH * 2) + ks * 32);
#pragma unroll
                for (int mt = 0; mt < 4; mt++)
#pragma unroll
                    for (int nt = 0; nt < 4; nt++)
                        mma_f16(acc[mt][nt], a[mt][0], a[mt][1], a[mt][2], a[mt][3],
                                b[nt][0], b[nt][1]);
            }
        }

        // epilogue: ReLU -> HD fp16, bias = CB3[b][n]
#pragma unroll
        for (int mt = 0; mt < 4; mt++) {
            int r = m0 + wm * 64 + mt * 16 + lg;
            const float* bp = CB3 + (size_t)((m0 + wm * 64 + mt * 16) >> 4) * HID;
#pragma unroll
            for (int nt = 0; nt < 4; nt++) {
                int cc = t * 128 + wn * 32 + nt * 8 + li * 2;
                float b0 = __ldg(bp + cc), b1 = __ldg(bp + cc + 1);
                float v0 = acc[mt][nt][0] + b0;
                float v1 = acc[mt][nt][1] + b1;
                float v2 = acc[mt][nt][2] + b0;
                float v3 = acc[mt][nt][3] + b1;
                *(__half2*)(HD + (size_t)r * HID + cc) =
                    __floats2half2_rn(fmaxf(v0, 0.f), fmaxf(v1, 0.f));
                *(__half2*)(HD + (size_t)(r + 8) * HID + cc) =
                    __floats2half2_rn(fmaxf(v2, 0.f), fmaxf(v3, 0.f));
            }
        }
    }
}

// ---------------- launch ----------------
extern "C" void kernel_launch(void* const* d_in, const int* in_sizes, int n_in,
                              void* d_out, int out_size) {
    const float* x      = (const float*)d_in[0];
    const float* c      = (const float*)d_in[1];
    const float* enc_w1 = (const float*)d_in[2];
    const float* enc_b1 = (const float*)d_in[3];
    const float* enc_w2 = (const float*)d_in[4];
    const float* enc_b2 = (const float*)d_in[5];
    const float* dec_w1 = (const float*)d_in[6];
    const float* dec_b1 = (const float*)d_in[7];
    const float* dec_w2 = (const float*)d_in[8];
    const float* dec_b2 = (const float*)d_in[9];
    float* out = (float*)d_out;

    __half *A1, *H, *A3, *HD, *W1, *W2, *W3, *W4;
    float *CB1, *CB3;
    cudaGetSymbolAddress((void**)&A1,  g_A1);
    cudaGetSymbolAddress((void**)&H,   g_H);
    cudaGetSymbolAddress((void**)&A3,  g_A3);
    cudaGetSymbolAddress((void**)&HD,  g_HD);
    cudaGetSymbolAddress((void**)&W1,  g_W1);
    cudaGetSymbolAddress((void**)&W2,  g_W2);
    cudaGetSymbolAddress((void**)&W3,  g_W3);
    cudaGetSymbolAddress((void**)&W4,  g_W4);
    cudaGetSymbolAddress((void**)&CB1, g_CB1);
    cudaGetSymbolAddress((void**)&CB3, g_CB3);

    cudaFuncSetAttribute(gemm_mma<0,1>, cudaFuncAttributeMaxDynamicSharedMemorySize, SMEM_GG);
    cudaFuncSetAttribute(gemm_mma<1,0>, cudaFuncAttributeMaxDynamicSharedMemorySize, SMEM_GG);
    cudaFuncSetAttribute(gemm_mma<2,0>, cudaFuncAttributeMaxDynamicSharedMemorySize, SMEM_GG);
    cudaFuncSetAttribute(gemm3p, cudaFuncAttributeMaxDynamicSharedMemorySize, SMEM_P);

    // fused prep (single launch)
    prep_all<<<PREP_BLKS, 256>>>(x, c, enc_w1, enc_b1, enc_w2, dec_w1, dec_b1, dec_w2);

    // GEMM1: A1[16384 x 768] * W1^T -> H (ReLU, fp16), bias = CB1[b][n]
    gemm_mma<0,1><<<dim3(HID / TNT, MROWS / TMT), NTH_S, SMEM_GG>>>(
        A1, PD, W1, CB1, H, nullptr, HID, PD / TKT);
    // GEMM2: H * W2^T -> mu_logvar (fp32, staged) + mu -> A3 (fp16), N=256
    gemm_mma<1,0><<<dim3((2 * LAT) / TNT, MROWS / TMT), NTH_S, SMEM_GG>>>(
        H, HID, W2, enc_b2, out + ML_OFFSET, A3, 0, HID / TKT);
    // GEMM3: persistent-A, grid=128, loops 8 W3 n-tiles
    gemm3p<<<MROWS / TMT, NTH_S, SMEM_P>>>(A3, W3, CB3, HD);
    // GEMM4: HD * W4^T -> sigmoid + depatchify (fp32, direct), N=768
    gemm_mma<2,0><<<dim3(PD / TNT, MROWS / TMT), NTH_S, SMEM_GG>>>(
        HD, HID, W4, dec_b2, out, nullptr, 0, HID / TKT);
}

// round 15
// speedup vs baseline: 1.0508x; 1.0238x over previous
#include <cuda_runtime.h>
#include <cuda_fp16.h>
#include <cstdint>
#include <math.h>

// ---------------- problem constants ----------------
#define BS     1024
#define CHN    3
#define IMG    64
#define KP     16
#define NC     10
#define HID    1024
#define LAT    128
#define LP     16
#define PD     768
#define MROWS  (BS * LP)        // 16384

#define RECON_ELEMS (BS * CHN * IMG * IMG)
#define ML_OFFSET   RECON_ELEMS

// GEMM tile: CTA 128x128xK64, 8 warps (2M x 4N), warp 64x32
#define TMT 128
#define TNT 128
#define TKT 64
#define NTH_S 256

#define ROWH 72                              // halves per row (64 + 8 pad)
#define SA_SZ (TMT * ROWH * 2)               // 18432 B
#define SB_SZ (TNT * ROWH * 2)               // 18432 B
#define STAGE_SZ (SA_SZ + SB_SZ)             // 36864 B
#define NSTAGE 3
#define SMEM_GG (NSTAGE * STAGE_SZ)          // 110592 B -> 2 CTA/SM

// ---------------- scratch ----------------
__device__ __half g_A1[(size_t)MROWS * PD];        // pure patches [16384][768]
__device__ __half g_H [(size_t)MROWS * HID];
__device__ __half g_A3[(size_t)MROWS * LAT];       // mu only [16384][128]
__device__ __half g_HD[(size_t)MROWS * HID];
__device__ __half g_W1[(size_t)HID * PD];          // enc_w1[0:768]^T
__device__ __half g_W2[(size_t)(2*LAT) * HID];     // enc_w2^T
__device__ __half g_W3[(size_t)HID * LAT];         // dec_w1[0:128]^T
__device__ __half g_W4[(size_t)PD * HID];          // dec_w2^T
__device__ float  g_CB1[(size_t)BS * HID];         // c@enc_w1[768:778] + enc_b1
__device__ float  g_CB3[(size_t)BS * HID];         // c@dec_w1[128:138] + dec_b1

// ---------------- helpers ----------------
__device__ __forceinline__ uint32_t smem_u32(const void* p) {
    uint32_t a;
    asm("{ .reg .u64 t; cvta.to.shared.u64 t, %1; cvt.u32.u64 %0, t; }"
        : "=r"(a) : "l"(p));
    return a;
}
#define CP16(dst, src) \
    asm volatile("cp.async.cg.shared.global [%0], [%1], 16;" :: "r"(dst), "l"(src) : "memory")
#define CP_COMMIT() asm volatile("cp.async.commit_group;" ::: "memory")
#define CP_WAIT(n)  asm volatile("cp.async.wait_group %0;" :: "n"(n) : "memory")

__device__ __forceinline__ void ldsm_x4(uint32_t& r0, uint32_t& r1, uint32_t& r2,
                                        uint32_t& r3, uint32_t addr) {
    asm volatile("ldmatrix.sync.aligned.m8n8.x4.shared.b16 {%0,%1,%2,%3}, [%4];"
                 : "=r"(r0), "=r"(r1), "=r"(r2), "=r"(r3) : "r"(addr));
}
__device__ __forceinline__ void mma_f16(float c[4],
                                        uint32_t a0, uint32_t a1, uint32_t a2, uint32_t a3,
                                        uint32_t b0, uint32_t b1) {
    asm volatile(
        "mma.sync.aligned.m16n8k16.row.col.f32.f16.f16.f32 "
        "{%0,%1,%2,%3}, {%4,%5,%6,%7}, {%8,%9}, {%0,%1,%2,%3};"
        : "+f"(c[0]), "+f"(c[1]), "+f"(c[2]), "+f"(c[3])
        : "r"(a0), "r"(a1), "r"(a2), "r"(a3), "r"(b0), "r"(b1));
}
__device__ __forceinline__ float fast_sigmoid(float x) {
    // 1/(1+exp(-x)) with approx rcp (err ~2^-22) — avoids IEEE-div slow path
    return __fdividef(1.0f, 1.0f + __expf(-x));
}

// ---------------- fused prep (one launch) ----------------
#define PREP_PATCH_BLKS 8192
#define PREP_TRANS_BLKS 1920
#define PREP_CB_BLKS    8192
#define PREP_BLKS (PREP_PATCH_BLKS + PREP_TRANS_BLKS + PREP_CB_BLKS)

__global__ __launch_bounds__(256)
void prep_all(const float* __restrict__ x, const float* __restrict__ c,
              const float* __restrict__ enc_w1, const float* __restrict__ enc_b1,
              const float* __restrict__ enc_w2,
              const float* __restrict__ dec_w1, const float* __restrict__ dec_b1,
              const float* __restrict__ dec_w2) {
    __shared__ float tile[32][33];
    int blk = blockIdx.x;
    int tid = threadIdx.x;

    if (blk < PREP_PATCH_BLKS) {
        int row = blk * 2 + (tid >> 7);
        int t = tid & 127;
        int b = row >> 4, l = row & 15;
        int oh = l >> 2, ow = l & 3;
        const float* xb = x + (size_t)b * (CHN * IMG * IMG);
        __half* arow = g_A1 + (size_t)row * PD;
        for (int j4 = t; j4 < PD / 4; j4 += 128) {
            int j = j4 * 4;
            int ch = j >> 8, kh = (j >> 4) & 15, kw = j & 15;
            float4 v = *(const float4*)(xb + ch * (IMG * IMG) + (oh * KP + kh) * IMG
                                        + ow * KP + kw);
            *(__half2*)(arow + j)     = __floats2half2_rn(v.x, v.y);
            *(__half2*)(arow + j + 2) = __floats2half2_rn(v.z, v.w);
        }
        return;
    }
    blk -= PREP_PATCH_BLKS;
    if (blk < PREP_TRANS_BLKS) {
        const float* W; __half* Wt; int K, N, Kpad, t;
        if (blk < 768)      { W = enc_w1; Wt = g_W1; K = PD;  N = HID;     Kpad = PD;  t = blk; }
        else if (blk < 1024){ W = enc_w2; Wt = g_W2; K = HID; N = 2 * LAT; Kpad = HID; t = blk - 768; }
        else if (blk < 1152){ W = dec_w1; Wt = g_W3; K = LAT; N = HID;     Kpad = LAT; t = blk - 1024; }
        else                { W = dec_w2; Wt = g_W4; K = HID; N = PD;      Kpad = HID; t = blk - 1152; }
        int ktiles = Kpad / 32;
        int kb = (t % ktiles) * 32, nb = (t / ktiles) * 32;
        int tx = tid & 31, ty = tid >> 5;
        for (int i = ty; i < 32; i += 8) {
            int k = kb + i;
            tile[i][tx] = (k < K) ? W[(size_t)k * N + nb + tx] : 0.0f;
        }
        __syncthreads();
        for (int i = ty; i < 32; i += 8)
            Wt[(size_t)(nb + i) * Kpad + kb + tx] = __float2half_rn(tile[tx][i]);
        return;
    }
    blk -= PREP_TRANS_BLKS;
    {
        int z = blk >> 12;
        int rem = blk & 4095;
        int b = rem >> 2;
        int n = (rem & 3) * 256 + tid;
        const float* W  = z ? dec_w1 : enc_w1;
        const float* bb = z ? dec_b1 : enc_b1;
        int krow = z ? LAT : PD;
        float* out = (z ? g_CB3 : g_CB1) + (size_t)b * HID + n;
        float acc = bb[n];
        const float* cb = c + b * NC;
#pragma unroll
        for (int j = 0; j < NC; j++)
            acc = fmaf(cb[j], W[(size_t)(krow + j) * HID + n], acc);
        *out = acc;
    }
}

// ---------------- round-9 GEMM: 256 thr, warp 64x32, 3-stage ---------------
// EPI 0: ReLU -> fp16 C (ldc)
// EPI 1: mu_logvar -> fp32 C ([b][f][l], staged) + mu -> fp16 C2 (stride LAT)
// EPI 2: sigmoid + depatchify -> fp32 C (direct scatter)
// BIASMAT 0: bias[n]; 1: bias[b][n] (ld = HID)
template <int EPI, int BIASMAT>
__global__ __launch_bounds__(NTH_S, 2)
void gemm_mma(const __half* __restrict__ A, int kpad,
              const __half* __restrict__ Bt,
              const float* __restrict__ bias,
              void* __restrict__ Cv, __half* __restrict__ C2,
              int ldc, int nchunks) {
    extern __shared__ char smem[];
    const uint32_t sb = smem_u32(smem);

    const int tid  = threadIdx.x;
    const int wid  = tid >> 5;
    const int lane = tid & 31;
    const int wm   = wid & 1;
    const int wn   = wid >> 1;
    const int m0   = blockIdx.y * TMT;
    const int n0   = blockIdx.x * TNT;

    const __half* Ab = A + (size_t)m0 * kpad;
    const __half* Bb = Bt + (size_t)n0 * kpad;

    const int lg = lane >> 2;
    const int li = lane & 3;

    float bv[4][2];
    if (BIASMAT == 0) {
#pragma unroll
        for (int nt = 0; nt < 4; nt++) {
            int cc = n0 + wn * 32 + nt * 8 + li * 2;
            bv[nt][0] = __ldg(bias + cc);
            bv[nt][1] = __ldg(bias + cc + 1);
        }
    }

    float acc[4][4][4];
#pragma unroll
    for (int i = 0; i < 4; i++)
#pragma unroll
        for (int j = 0; j < 4; j++)
#pragma unroll
            for (int q = 0; q < 4; q++) acc[i][j][q] = 0.0f;

    auto load_tiles = [&](int stage, int kb) {
        uint32_t adst = sb + stage * STAGE_SZ;
        uint32_t bdst = adst + SA_SZ;
#pragma unroll
        for (int o = 0; o < 4; o++) {
            int e = o * NTH_S + tid;
            int r = e >> 3, cc = e & 7;
            CP16(adst + r * (ROWH * 2) + cc * 16,
                 Ab + (size_t)r * kpad + kb + cc * 8);
        }
#pragma unroll
        for (int o = 0; o < 4; o++) {
            int e = o * NTH_S + tid;
            int r = e >> 3, cc = e & 7;
            CP16(bdst + r * (ROWH * 2) + cc * 16,
                 Bb + (size_t)r * kpad + kb + cc * 8);
        }
    };

    load_tiles(0, 0);
    CP_COMMIT();
    load_tiles(1, TKT);
    CP_COMMIT();

    const uint32_t aOff = (uint32_t)(wm * 64 + (lane & 15)) * (ROWH * 2) + (lane >> 4) * 16;
    const uint32_t bOff = SA_SZ +
        (uint32_t)(wn * 32 + (lane & 7) + ((lane >> 4) & 1) * 8) * (ROWH * 2)
        + ((lane >> 3) & 1) * 16;

    for (int it = 0; it < nchunks; ++it) {
        if (it + 1 < nchunks) CP_WAIT(1); else CP_WAIT(0);
        __syncthreads();
        if (it + 2 < nchunks) {
            load_tiles((it + 2) % NSTAGE, (it + 2) * TKT);
            CP_COMMIT();
        }

        const uint32_t stg = sb + (it % NSTAGE) * STAGE_SZ;
        const uint32_t aB = stg + aOff;
        const uint32_t bB = stg + bOff;

#pragma unroll
        for (int ks = 0; ks < 4; ks++) {
            uint32_t a[4][4];
#pragma unroll
            for (int mt = 0; mt < 4; mt++)
                ldsm_x4(a[mt][0], a[mt][1], a[mt][2], a[mt][3],
                        aB + mt * (16 * ROWH * 2) + ks * 32);
            uint32_t b[4][2];
#pragma unroll
            for (int p = 0; p < 2; p++)
                ldsm_x4(b[2*p][0], b[2*p][1], b[2*p+1][0], b[2*p+1][1],
                        bB + p * (16 * ROWH * 2) + ks * 32);
#pragma unroll
            for (int mt = 0; mt < 4; mt++)
#pragma unroll
                for (int nt = 0; nt < 4; nt++)
                    mma_f16(acc[mt][nt], a[mt][0], a[mt][1], a[mt][2], a[mt][3],
                            b[nt][0], b[nt][1]);
        }
    }

    // ---------------- epilogue ----------------
    if (EPI == 1) {
        __syncthreads();
        float* sm = (float*)smem;   // [b_local(8)][f_local(128) stride 20][l(16)]
#pragma unroll
        for (int mt = 0; mt < 4; mt++) {
            int lr = wm * 64 + mt * 16 + lg;
            int bl = lr >> 4;
            int l  = lr & 15;
            int r  = m0 + lr;
#pragma unroll
            for (int nt = 0; nt < 4; nt++) {
                int fl = wn * 32 + nt * 8 + li * 2;
                int cc = n0 + fl;
                float v0 = acc[mt][nt][0] + bv[nt][0];
                float v1 = acc[mt][nt][1] + bv[nt][1];
                float v2 = acc[mt][nt][2] + bv[nt][0];
                float v3 = acc[mt][nt][3] + bv[nt][1];
                sm[bl * 2560 + fl * 20 + l]           = v0;
                sm[bl * 2560 + (fl + 1) * 20 + l]     = v1;
                sm[bl * 2560 + fl * 20 + l + 8]       = v2;
                sm[bl * 2560 + (fl + 1) * 20 + l + 8] = v3;
                if (cc < LAT) {
                    *(__half2*)(C2 + (size_t)r * LAT + cc) = __floats2half2_rn(v0, v1);
                    *(__half2*)(C2 + (size_t)(r + 8) * LAT + cc) = __floats2half2_rn(v2, v3);
                }
            }
        }
        __syncthreads();
        float* C = (float*)Cv + (size_t)(m0 >> 4) * (2 * LAT * LP) + n0 * LP;
#pragma unroll
        for (int o = 0; o < 16; o++) {
            int e = o * NTH_S + tid;
            int l4 = e & 3, f = (e >> 2) & 127, b = e >> 9;
            float4 v = *(float4*)(sm + b * 2560 + f * 20 + l4 * 4);
            *(float4*)(C + (size_t)b * (2 * LAT * LP) + f * LP + l4 * 4) = v;
        }
        return;
    }

#pragma unroll
    for (int mt = 0; mt < 4; mt++) {
        int r = m0 + wm * 64 + mt * 16 + lg;
        const float* bp = BIASMAT ? (bias + (size_t)((m0 + wm * 64 + mt * 16) >> 4) * HID)
                                  : nullptr;
#pragma unroll
        for (int nt = 0; nt < 4; nt++) {
            int cc = n0 + wn * 32 + nt * 8 + li * 2;
            float b0, b1;
            if (BIASMAT) { b0 = __ldg(bp + cc); b1 = __ldg(bp + cc + 1); }
            else         { b0 = bv[nt][0];      b1 = bv[nt][1]; }
            float v0 = acc[mt][nt][0] + b0;
            float v1 = acc[mt][nt][1] + b1;
            float v2 = acc[mt][nt][2] + b0;
            float v3 = acc[mt][nt][3] + b1;

            if (EPI == 0) {
                __half* C = (__half*)Cv;
                *(__half2*)(C + (size_t)r * ldc + cc) =
                    __floats2half2_rn(fmaxf(v0, 0.f), fmaxf(v1, 0.f));
                *(__half2*)(C + (size_t)(r + 8) * ldc + cc) =
                    __floats2half2_rn(fmaxf(v2, 0.f), fmaxf(v3, 0.f));
            } else {
                float* C = (float*)Cv;
                v0 = fast_sigmoid(v0);
                v1 = fast_sigmoid(v1);
                v2 = fast_sigmoid(v2);
                v3 = fast_sigmoid(v3);
                int ch = cc >> 8, kh = (cc >> 4) & 15, kw = cc & 15;
                {
                    int b_ = r >> 4, l = r & 15;
                    int oh = l >> 2, ow = l & 3;
                    float* op = C + (size_t)b_ * (CHN * IMG * IMG) + ch * (IMG * IMG)
                              + (oh * KP + kh) * IMG + ow * KP + kw;
                    *(float2*)op = make_float2(v0, v1);
                }
                {
                    int rr = r + 8;
                    int b_ = rr >> 4, l = rr & 15;
                    int oh = l >> 2, ow = l & 3;
                    float* op = C + (size_t)b_ * (CHN * IMG * IMG) + ch * (IMG * IMG)
                              + (oh * KP + kh) * IMG + ow * KP + kw;
                    *(float2*)op = make_float2(v2, v3);
                }
            }
        }
    }
}

// ---------------- launch ----------------
extern "C" void kernel_launch(void* const* d_in, const int* in_sizes, int n_in,
                              void* d_out, int out_size) {
    const float* x      = (const float*)d_in[0];
    const float* c      = (const float*)d_in[1];
    const float* enc_w1 = (const float*)d_in[2];
    const float* enc_b1 = (const float*)d_in[3];
    const float* enc_w2 = (const float*)d_in[4];
    const float* enc_b2 = (const float*)d_in[5];
    const float* dec_w1 = (const float*)d_in[6];
    const float* dec_b1 = (const float*)d_in[7];
    const float* dec_w2 = (const float*)d_in[8];
    const float* dec_b2 = (const float*)d_in[9];
    float* out = (float*)d_out;

    __half *A1, *H, *A3, *HD, *W1, *W2, *W3, *W4;
    float *CB1, *CB3;
    cudaGetSymbolAddress((void**)&A1,  g_A1);
    cudaGetSymbolAddress((void**)&H,   g_H);
    cudaGetSymbolAddress((void**)&A3,  g_A3);
    cudaGetSymbolAddress((void**)&HD,  g_HD);
    cudaGetSymbolAddress((void**)&W1,  g_W1);
    cudaGetSymbolAddress((void**)&W2,  g_W2);
    cudaGetSymbolAddress((void**)&W3,  g_W3);
    cudaGetSymbolAddress((void**)&W4,  g_W4);
    cudaGetSymbolAddress((void**)&CB1, g_CB1);
    cudaGetSymbolAddress((void**)&CB3, g_CB3);

    cudaFuncSetAttribute(gemm_mma<0,1>, cudaFuncAttributeMaxDynamicSharedMemorySize, SMEM_GG);
    cudaFuncSetAttribute(gemm_mma<1,0>, cudaFuncAttributeMaxDynamicSharedMemorySize, SMEM_GG);
    cudaFuncSetAttribute(gemm_mma<2,0>, cudaFuncAttributeMaxDynamicSharedMemorySize, SMEM_GG);

    // fused prep (single launch)
    prep_all<<<PREP_BLKS, 256>>>(x, c, enc_w1, enc_b1, enc_w2, dec_w1, dec_b1, dec_w2);

    // GEMM1: A1[16384 x 768] * W1^T -> H (ReLU, fp16), bias = CB1[b][n]
    gemm_mma<0,1><<<dim3(HID / TNT, MROWS / TMT), NTH_S, SMEM_GG>>>(
        A1, PD, W1, CB1, H, nullptr, HID, PD / TKT);
    // GEMM2: H * W2^T -> mu_logvar (fp32, staged) + mu -> A3 (fp16), N=256
    gemm_mma<1,0><<<dim3((2 * LAT) / TNT, MROWS / TMT), NTH_S, SMEM_GG>>>(
        H, HID, W2, enc_b2, out + ML_OFFSET, A3, 0, HID / TKT);
    // GEMM3: A3[16384 x 128] * W3^T -> HD (ReLU, fp16), bias = CB3[b][n]
    gemm_mma<0,1><<<dim3(HID / TNT, MROWS / TMT), NTH_S, SMEM_GG>>>(
        A3, LAT, W3, CB3, HD, nullptr, HID, LAT / TKT);
    // GEMM4: HD * W4^T -> sigmoid + depatchify (fp32, direct), N=768
    gemm_mma<2,0><<<dim3(PD / TNT, MROWS / TMT), NTH_S, SMEM_GG>>>(
        HD, HID, W4, dec_b2, out, nullptr, 0, HID / TKT);
}